// round 8
// baseline (speedup 1.0000x reference)
#include <cuda_runtime.h>
#include <math.h>

#define N_    256
#define B_    64
#define FIN   5
#define NE_   65536
#define NC_   (B_ * FIN)     // 320 columns in the [c][node] layout

// ---------------- scratch (no allocations allowed) ----------------
__device__ __align__(16) float g_S[4 * NE_];    // S0, SA, S1, S2  (0.1I + 0.45*M)
__device__ __align__(16) float g_X0[NC_ * N_];  // ping
__device__ __align__(16) float g_X1[NC_ * N_];  // pong
__device__ float g_dis[N_];
__device__ float g_logits[3];                   // logits / (0.6*ln2)

// ---------------- packed f32x2 helpers ----------------
static __device__ __forceinline__ unsigned long long ffma2(unsigned long long a,
                                                           unsigned long long b,
                                                           unsigned long long c) {
    unsigned long long d;
    asm("fma.rn.f32x2 %0, %1, %2, %3;" : "=l"(d) : "l"(a), "l"(b), "l"(c));
    return d;
}
static __device__ __forceinline__ unsigned long long fadd2(unsigned long long a,
                                                           unsigned long long b) {
    unsigned long long d;
    asm("add.rn.f32x2 %0, %1, %2;" : "=l"(d) : "l"(a), "l"(b));
    return d;
}
static __device__ __forceinline__ unsigned long long dup2(float v) {
    unsigned long long d;
    unsigned int u = __float_as_uint(v);
    asm("mov.b64 %0, {%1, %1};" : "=l"(d) : "r"(u));
    return d;
}
static __device__ __forceinline__ float2 unpack2(unsigned long long v) {
    unsigned int lo, hi;
    asm("mov.b64 {%0, %1}, %2;" : "=r"(lo), "=r"(hi) : "l"(v));
    return make_float2(__uint_as_float(lo), __uint_as_float(hi));
}

// ---------------- FMA-pipe transcendentals (no MUFU) ----------------
static __device__ __forceinline__ float fast_lg2(float x) {
    int b = __float_as_int(x);
    int i = (b - 0x3f3504f3) & 0xff800000;
    float m = __int_as_float(b - i);
    float e = (float)(i >> 23);
    float t = m - 1.0f;
    float z = t * t;
    float p =  7.0376836292e-2f;
    p = p * t - 1.1514610310e-1f;
    p = p * t + 1.1676998740e-1f;
    p = p * t - 1.2420140846e-1f;
    p = p * t + 1.4249322787e-1f;
    p = p * t - 1.6668057665e-1f;
    p = p * t + 2.0000714765e-1f;
    p = p * t - 2.4999993993e-1f;
    p = p * t + 3.3333331174e-1f;
    float lnm = t + (t * z * p - 0.5f * z);
    return e + lnm * 1.4426950409f;
}
static __device__ __forceinline__ float fast_ex2(float v) {
    v = fminf(fmaxf(v, -100.0f), 100.0f);
    int iv = __float2int_rd(v);
    float f = v - (float)iv;
    float p = 1.52527338e-5f;
    p = p * f + 1.54035304e-4f;
    p = p * f + 1.33335581e-3f;
    p = p * f + 9.61812911e-3f;
    p = p * f + 5.55041087e-2f;
    p = p * f + 2.40226507e-1f;
    p = p * f + 6.93147181e-1f;
    p = p * f + 1.0f;
    return p * __int_as_float((iv + 127) << 23);
}
static __device__ __forceinline__ float fast_rcp(float d) {
    float r = __int_as_float(0x7EF311C3 - __float_as_int(d));
    r = r * (2.0f - d * r);
    r = r * (2.0f - d * r);
    r = r * (2.0f - d * r);
    return r;
}

// ---------------- digamma (fp32) ----------------
static __device__ float digamma_f(float x) {
    float r = 0.0f;
    while (x < 8.0f) { r -= __fdividef(1.0f, x); x += 1.0f; }
    float f = __fdividef(1.0f, x * x);
    float s = f * (1.0f / 12.0f - f * (1.0f / 120.0f - f * (1.0f / 252.0f
            - f * (1.0f / 240.0f - f * (1.0f / 132.0f)))));
    return r + logf(x) - 0.5f / x - s;
}

// ---------------- kernel 1: degree/dis (32 blocks) + scalar block (block 32) --
__global__ void __launch_bounds__(256) deg_scalar_kernel(
        const float* __restrict__ ewp,
        const float* __restrict__ a_uc,
        const float* __restrict__ b_uc,
        const float* __restrict__ u_pi,
        float* __restrict__ out) {
    int b = blockIdx.x, t = threadIdx.x;
    if (b == 32) {
        __shared__ float kld_s[3];
        if (t < 3) {
            int l = t;
            float au = a_uc[l]; if (au < -10.0f) au = -10.0f;
            float bu = b_uc[l]; if (bu < -10.0f) bu = -10.0f; if (bu > 50.0f) bu = 50.0f;
            float a = log1pf(expf(au));
            float bb = log1pf(expf(bu));
            float up = u_pi[l];
            up = fminf(fmaxf(up, 1e-6f), 1.0f - 1e-6f);
            float pi = powf(1.0f - powf(up, 1.0f / bb), 1.0f / a);
            g_logits[l] = (logf(pi) - log1pf(-pi)) * (1.0f / (0.6f * 0.6931471806f));
            out[193 + l] = pi;   // drop_rates
            const float euler = 0.577215664901532f;
            kld_s[l] = (1.0f - 0.8f / a) * (-euler - digamma_f(bb) - 1.0f / bb)
                     + logf(a * bb + 1e-10f) - logf(0.8f) - (bb - 1.0f) / bb;
        }
        __syncthreads();
        if (t == 0) out[192] = kld_s[0] + kld_s[1] + kld_s[2];   // kld_loss
        return;
    }
    int w = t >> 5, l = t & 31;
    int r = b * 8 + w;
    float s = 0.f;
    #pragma unroll
    for (int jj = 0; jj < 8; jj++) {
        int j = l + jj * 32;
        int hi = max(r, j), lo = min(r, j);
        s += fabsf(ewp[(hi * (hi + 1)) / 2 + lo]);
    }
    #pragma unroll
    for (int o = 16; o > 0; o >>= 1) s += __shfl_xor_sync(0xffffffffu, s, o);
    if (l == 0) g_dis[r] = (s > 0.f) ? rsqrtf(s) : 0.f;
}

// ---------------- kernel 2: S matrices (blocks 0..255) + X transpose (256..319)
__global__ void __launch_bounds__(256) mats_kernel(const float* __restrict__ ewp,
                                                   const float* __restrict__ u_rb,
                                                   const float* __restrict__ x) {
    if (blockIdx.x >= 256) {   // transpose x[b*256+i][f] -> g_X0[b*5+f][i]
        int b = blockIdx.x - 256;
        int i = threadIdx.x;
        const float* xb = x + (b * 256 + i) * FIN;
        #pragma unroll
        for (int f = 0; f < FIN; f++)
            g_X0[(b * FIN + f) * 256 + i] = xb[f];
        return;
    }
    int i = blockIdx.x, j = threadIdx.x;
    int r = max(i, j), c = min(i, j);
    float w = ewp[(r * (r + 1)) / 2 + c];
    float aij = g_dis[i] * w * g_dis[j];
    int e = i * N_ + j;
    float diag = (i == j) ? 0.1f : 0.0f;
    g_S[1 * NE_ + e] = 0.45f * aij + diag;                        // SA
    #pragma unroll
    for (int l = 0; l < 3; l++) {
        float ur = u_rb[l * NE_ + e];
        ur = fminf(fmaxf(ur, 1e-6f), 1.0f - 1e-6f);
        float L = (fast_lg2(ur) - fast_lg2(1.0f - ur)) * (1.0f / 0.6f);
        float v = -(g_logits[l] + L);
        float z = fast_rcp(1.0f + fast_ex2(v));
        int slot = (l == 0) ? 0 : (l + 1);                        // S0, S1, S2
        g_S[slot * NE_ + e] = 0.45f * z * aij + diag;
    }
}

// ---------------- kernel 3: all 5 conv stages in ONE kernel, 8-CTA clusters ---
// 128 blocks = 16 c-groups (clusters) x 8 j-tiles. 640 threads (20 warps).
// Per stage: Y[c][j] = sum_k M_s[k][j] X[c][k] over c-tile 20, j-tile 32.
// Cross-stage dependency closes inside the cluster (same c-rows, all j-tiles)
// -> barrier.cluster between stages; X exchanged via L2 (st.global + cp.async.cg,
// which bypasses L1 so the ping-pong never reads stale lines).
// K-slab for stage s+1 prefetches (double-buffered cp.async) during stage s.
#define C5_KS0   0          // 256*32 f32 = 32768
#define C5_KS1   32768      // 32768
#define C5_XS    65536      // 20*260 f32 = 20800
#define C5_PS    86336      // 4*320 u64  = 10240
#define C5_SMEM  96576

__global__ void __launch_bounds__(640, 1) __cluster_dims__(8, 1, 1)
conv5_kernel() {
    extern __shared__ __align__(16) char sm[];
    float*              Xs = (float*)(sm + C5_XS);                // [20][260]
    unsigned long long* Ps = (unsigned long long*)(sm + C5_PS);   // [4][320]

    const int t  = threadIdx.x;
    const int bx = blockIdx.x;
    const int cg = bx >> 3, jt = bx & 7;
    const int c0 = cg * 20, j0 = jt * 32;

    const float* Ms[5] = { g_S, g_S + NE_, g_S + 2 * NE_, g_S + NE_, g_S + 3 * NE_ };

    // issue one 256x32 K-slab into buffer `buf` (2048 16B segments)
    auto issue_K = [&](const float* M, int buf) {
        char* base = sm + (buf ? C5_KS1 : C5_KS0);
        #pragma unroll
        for (int it = 0; it < 4; it++) {
            int idx = it * 640 + t;
            if (idx < 2048) {
                int row = idx >> 3, sg = idx & 7;
                const float* src = M + row * 256 + j0 + sg * 4;
                unsigned dst = (unsigned)__cvta_generic_to_shared(base + (row * 32 + sg * 4) * 4);
                asm volatile("cp.async.cg.shared.global [%0], [%1], 16;" :: "r"(dst), "l"(src));
            }
        }
        asm volatile("cp.async.commit_group;" ::: "memory");
    };
    // issue X c-rows (20 x 256 f32 = 1280 16B segments)
    auto issue_X = [&](const float* Xin) {
        #pragma unroll
        for (int it = 0; it < 2; it++) {
            int idx = it * 640 + t;
            int row = idx >> 6, sg = idx & 63;
            const float* src = Xin + (c0 + row) * 256 + sg * 4;
            unsigned dst = (unsigned)__cvta_generic_to_shared((char*)Xs + row * 1040 + sg * 16);
            asm volatile("cp.async.cg.shared.global [%0], [%1], 16;" :: "r"(dst), "l"(src));
        }
        asm volatile("cp.async.commit_group;" ::: "memory");
    };

    // prologue: K_0 then X_0
    issue_K(Ms[0], 0);
    issue_X(g_X0);

    const int ks = t / 160;      // warp-uniform K-split (4)
    const int r  = t % 160;
    const int c  = r >> 3;       // 0..19
    const int j4 = r & 7;        // 0..7 (4 columns each)
    const float* xrow = Xs + c * 260;

    #pragma unroll 1
    for (int s = 0; s < 5; s++) {
        if (s < 4) issue_K(Ms[s + 1], (s + 1) & 1);
        if (s < 4) { asm volatile("cp.async.wait_group 1;" ::: "memory"); }
        else       { asm volatile("cp.async.wait_group 0;" ::: "memory"); }
        __syncthreads();

        const float* kk = (const float*)(sm + ((s & 1) ? C5_KS1 : C5_KS0)) + j4 * 4;
        unsigned long long a0 = 0ull, a1 = 0ull;
        int k0 = ks * 64;
        #pragma unroll 8
        for (int k = k0; k < k0 + 64; k++) {
            unsigned long long xd = dup2(xrow[k]);
            ulonglong2 kq = *(const ulonglong2*)(kk + k * 32);
            a0 = ffma2(kq.x, xd, a0);
            a1 = ffma2(kq.y, xd, a1);
        }
        {
            ulonglong2 v; v.x = a0; v.y = a1;
            *(ulonglong2*)&Ps[(ks * 160 + r) * 2] = v;
        }
        __syncthreads();

        // combine 4 K-splits + optional relu + store Y slice (coalesced float2)
        float* wb = (s & 1) ? g_X0 : g_X1;
        if (t < 320) {
            unsigned long long su = fadd2(fadd2(Ps[t], Ps[320 + t]),
                                          fadd2(Ps[640 + t], Ps[960 + t]));
            float2 sv = unpack2(su);
            if (s == 2) { sv.x = fmaxf(sv.x, 0.f); sv.y = fmaxf(sv.y, 0.f); }
            int cc = t >> 4, jpg = t & 15;
            *(float2*)&wb[(c0 + cc) * 256 + j0 + jpg * 2] = sv;
        }
        __threadfence();
        asm volatile("barrier.cluster.arrive.aligned;" ::: "memory");
        asm volatile("barrier.cluster.wait.aligned;" ::: "memory");

        if (s < 4) issue_X((s & 1) ? g_X0 : g_X1);   // next stage reads what we just wrote
    }
}

// ---------------- kernel 4: head (one block per graph, 512 threads) ----------
__global__ void __launch_bounds__(512) head_kernel(
        const float* __restrict__ lin_w, const float* __restrict__ lin_b,
        const float* __restrict__ fc_w,  const float* __restrict__ fc_b,
        float* __restrict__ out) {
    __shared__ float Os[FIN][260];
    __shared__ float Pool[4][128];
    __shared__ float PP[128];
    int b = blockIdx.x, t = threadIdx.x;
    const float* O = g_X1;   // final stage output
    for (int idx = t; idx < FIN * 256; idx += 512) {
        int f = idx >> 8, n = idx & 255;
        Os[f][n] = O[(b * FIN + f) * 256 + n];
    }
    __syncthreads();
    {
        int k = t & 127, h = t >> 7;
        unsigned long long lw[FIN];
        #pragma unroll
        for (int f = 0; f < FIN; f++) lw[f] = dup2(lin_w[f * 128 + k]);
        unsigned long long lb2 = dup2(lin_b[k]);
        float s = 0.f;
        int n0 = h * 64;
        #pragma unroll 4
        for (int n = n0; n < n0 + 64; n += 2) {
            unsigned long long v2 = lb2;
            #pragma unroll
            for (int f = 0; f < FIN; f++) {
                unsigned long long o2 = *(const unsigned long long*)&Os[f][n];
                v2 = ffma2(o2, lw[f], v2);
            }
            float2 vv = unpack2(v2);
            s += fmaxf(vv.x, 0.f) + fmaxf(vv.y, 0.f);
        }
        Pool[h][k] = s;
    }
    __syncthreads();
    if (t < 128) PP[t] = Pool[0][t] + Pool[1][t] + Pool[2][t] + Pool[3][t];
    __syncthreads();
    if (t < 3) {
        float s = fc_b[t];
        for (int k2 = 0; k2 < 128; k2++)
            s = fmaf(PP[k2], fc_w[k2 * 3 + t], s);
        out[b * 3 + t] = s;
    }
}

// ---------------- launch ----------------
extern "C" void kernel_launch(void* const* d_in, const int* in_sizes, int n_in,
                              void* d_out, int out_size) {
    const float* x     = (const float*)d_in[0];
    const float* ewp   = (const float*)d_in[1];
    const float* a_uc  = (const float*)d_in[2];
    const float* b_uc  = (const float*)d_in[3];
    const float* u_pi  = (const float*)d_in[4];
    const float* u_rb  = (const float*)d_in[5];
    const float* lin_w = (const float*)d_in[6];
    const float* lin_b = (const float*)d_in[7];
    const float* fc_w  = (const float*)d_in[8];
    const float* fc_b  = (const float*)d_in[9];
    // d_in[10] = edge_index, d_in[11] = batch: structure is analytic, unused.
    float* out = (float*)d_out;

    cudaFuncSetAttribute(conv5_kernel,
                         cudaFuncAttributeMaxDynamicSharedMemorySize, C5_SMEM);

    deg_scalar_kernel<<<33, 256>>>(ewp, a_uc, b_uc, u_pi, out);
    mats_kernel<<<320, 256>>>(ewp, u_rb, x);
    conv5_kernel<<<128, 640, C5_SMEM>>>();
    head_kernel<<<B_, 512>>>(lin_w, lin_b, fc_w, fc_b, out);
}

// round 9
// speedup vs baseline: 1.9292x; 1.9292x over previous
#include <cuda_runtime.h>
#include <math.h>

#define N_    256
#define B_    64
#define FIN   5
#define NE_   65536

// ---------------- scratch (no allocations allowed) ----------------
__device__ __align__(16) float g_mats[4 * NE_];   // [A, M0, M1, M2], row-major [i*N+j]
__device__ float g_dis[N_];
__device__ float g_logits[3];                     // logits / (0.6*ln2)

// ---------------- packed f32x2 helpers ----------------
static __device__ __forceinline__ unsigned long long ffma2(unsigned long long a,
                                                           unsigned long long b,
                                                           unsigned long long c) {
    unsigned long long d;
    asm("fma.rn.f32x2 %0, %1, %2, %3;" : "=l"(d) : "l"(a), "l"(b), "l"(c));
    return d;
}
static __device__ __forceinline__ unsigned long long fadd2(unsigned long long a,
                                                           unsigned long long b) {
    unsigned long long d;
    asm("add.rn.f32x2 %0, %1, %2;" : "=l"(d) : "l"(a), "l"(b));
    return d;
}
static __device__ __forceinline__ unsigned long long dup2(float v) {
    unsigned long long d;
    unsigned int u = __float_as_uint(v);
    asm("mov.b64 %0, {%1, %1};" : "=l"(d) : "r"(u));
    return d;
}
static __device__ __forceinline__ float2 unpack2(unsigned long long v) {
    unsigned int lo, hi;
    asm("mov.b64 {%0, %1}, %2;" : "=r"(lo), "=r"(hi) : "l"(v));
    return make_float2(__uint_as_float(lo), __uint_as_float(hi));
}

// ---------------- FMA-pipe transcendentals (no MUFU) ----------------
static __device__ __forceinline__ float fast_lg2(float x) {
    int b = __float_as_int(x);
    int i = (b - 0x3f3504f3) & 0xff800000;
    float m = __int_as_float(b - i);
    float e = (float)(i >> 23);
    float t = m - 1.0f;
    float z = t * t;
    float p =  7.0376836292e-2f;
    p = p * t - 1.1514610310e-1f;
    p = p * t + 1.1676998740e-1f;
    p = p * t - 1.2420140846e-1f;
    p = p * t + 1.4249322787e-1f;
    p = p * t - 1.6668057665e-1f;
    p = p * t + 2.0000714765e-1f;
    p = p * t - 2.4999993993e-1f;
    p = p * t + 3.3333331174e-1f;
    float lnm = t + (t * z * p - 0.5f * z);
    return e + lnm * 1.4426950409f;
}
static __device__ __forceinline__ float fast_ex2(float v) {
    v = fminf(fmaxf(v, -100.0f), 100.0f);
    int iv = __float2int_rd(v);
    float f = v - (float)iv;
    float p = 1.52527338e-5f;
    p = p * f + 1.54035304e-4f;
    p = p * f + 1.33335581e-3f;
    p = p * f + 9.61812911e-3f;
    p = p * f + 5.55041087e-2f;
    p = p * f + 2.40226507e-1f;
    p = p * f + 6.93147181e-1f;
    p = p * f + 1.0f;
    return p * __int_as_float((iv + 127) << 23);
}
static __device__ __forceinline__ float fast_rcp(float d) {
    float r = __int_as_float(0x7EF311C3 - __float_as_int(d));
    r = r * (2.0f - d * r);
    r = r * (2.0f - d * r);
    r = r * (2.0f - d * r);
    return r;
}

// ---------------- digamma (fp32) ----------------
static __device__ float digamma_f(float x) {
    float r = 0.0f;
    while (x < 8.0f) { r -= __fdividef(1.0f, x); x += 1.0f; }
    float f = __fdividef(1.0f, x * x);
    float s = f * (1.0f / 12.0f - f * (1.0f / 120.0f - f * (1.0f / 252.0f
            - f * (1.0f / 240.0f - f * (1.0f / 132.0f)))));
    return r + logf(x) - 0.5f / x - s;
}

// ---------------- kernel 1: degree/dis (32 blocks) + scalar block (block 32) --
__global__ void __launch_bounds__(256) deg_scalar_kernel(
        const float* __restrict__ ewp,
        const float* __restrict__ a_uc,
        const float* __restrict__ b_uc,
        const float* __restrict__ u_pi,
        float* __restrict__ out) {
    int b = blockIdx.x, t = threadIdx.x;
    if (b == 32) {
        __shared__ float kld_s[3];
        if (t < 3) {
            int l = t;
            float au = a_uc[l]; if (au < -10.0f) au = -10.0f;
            float bu = b_uc[l]; if (bu < -10.0f) bu = -10.0f; if (bu > 50.0f) bu = 50.0f;
            float a = log1pf(expf(au));
            float bb = log1pf(expf(bu));
            float up = u_pi[l];
            up = fminf(fmaxf(up, 1e-6f), 1.0f - 1e-6f);
            float pi = powf(1.0f - powf(up, 1.0f / bb), 1.0f / a);
            g_logits[l] = (logf(pi) - log1pf(-pi)) * (1.0f / (0.6f * 0.6931471806f));
            out[193 + l] = pi;   // drop_rates
            const float euler = 0.577215664901532f;
            kld_s[l] = (1.0f - 0.8f / a) * (-euler - digamma_f(bb) - 1.0f / bb)
                     + logf(a * bb + 1e-10f) - logf(0.8f) - (bb - 1.0f) / bb;
        }
        __syncthreads();
        if (t == 0) out[192] = kld_s[0] + kld_s[1] + kld_s[2];   // kld_loss
        return;
    }
    int w = t >> 5, l = t & 31;
    int r = b * 8 + w;
    float s = 0.f;
    #pragma unroll
    for (int jj = 0; jj < 8; jj++) {
        int j = l + jj * 32;
        int hi = max(r, j), lo = min(r, j);
        s += fabsf(ewp[(hi * (hi + 1)) / 2 + lo]);
    }
    #pragma unroll
    for (int o = 16; o > 0; o >>= 1) s += __shfl_xor_sync(0xffffffffu, s, o);
    if (l == 0) g_dis[r] = (s > 0.f) ? rsqrtf(s) : 0.f;
}

// ---------------- kernel 2: build A and the three masked matrices (fast math) -
__global__ void __launch_bounds__(256) mats_kernel(const float* __restrict__ ewp,
                                                   const float* __restrict__ u_rb) {
    int i = blockIdx.x, j = threadIdx.x;
    int r = max(i, j), c = min(i, j);
    float w = ewp[(r * (r + 1)) / 2 + c];
    float aij = g_dis[i] * w * g_dis[j];
    int e = i * N_ + j;
    g_mats[e] = aij;
    #pragma unroll
    for (int l = 0; l < 3; l++) {
        float ur = u_rb[l * NE_ + e];
        ur = fminf(fmaxf(ur, 1e-6f), 1.0f - 1e-6f);
        float L = (fast_lg2(ur) - fast_lg2(1.0f - ur)) * (1.0f / 0.6f);
        float v = -(g_logits[l] + L);
        float z = fast_rcp(1.0f + fast_ex2(v));
        g_mats[(l + 1) * NE_ + e] = z * aij;
    }
}

// ---------------- kernel 3: fused 5-conv chain + head, clustered, 1024 thr ----
// 128 blocks = (graph b = blockIdx.x>>1, column half c = blockIdx.x&1),
// cluster (2,1,1), 1024 threads (32 warps -> ~50% occ).
// Thread t: j2 = t&63 (cols 2j2, 2j2+1 of the 128-col slab), ks = t>>6
// (16 K-splits; 8 rows in each Mtile half). Matrix slabs stream via cp.async
// double-buffered 64KB halves; X exchanged with peer CTA via DSMEM.
#define SM_MTILE   0          // 2 * 128*128 f32 = 131072
#define SM_XD      131072     // 256*6 u64       = 12288
#define SM_XP      143360     // 256*5 f32       = 5120
#define SM_PS      148480     // 320*18 u64      = 46080
#define SM_POOL    194560     // 8*128 f32       = 4096
#define SM_POOLP   198656     // 128 f32         = 512
#define SM_TOTAL   199168

__global__ void __launch_bounds__(1024, 1) __cluster_dims__(2, 1, 1)
conv_head_kernel(const float* __restrict__ x,
                 const float* __restrict__ lin_w, const float* __restrict__ lin_b,
                 const float* __restrict__ fc_w,  const float* __restrict__ fc_b,
                 float* __restrict__ out) {
    extern __shared__ __align__(16) char sm_[];
    float*              Mtile = (float*)(sm_ + SM_MTILE);
    unsigned long long* Xd    = (unsigned long long*)(sm_ + SM_XD);
    float*              Xp    = (float*)(sm_ + SM_XP);
    unsigned long long* Ps    = (unsigned long long*)(sm_ + SM_PS);   // [320][18]
    float*              Pool  = (float*)(sm_ + SM_POOL);
    float*              PoolP = (float*)(sm_ + SM_POOLP);

    const int t  = threadIdx.x;
    const int j2 = t & 63;              // 2-col group within the 128-col slab
    const int ks = t >> 6;              // 0..15 K-split (8 rows per half)
    const int b  = blockIdx.x >> 1;
    const int c  = blockIdx.x & 1;      // == cluster rank
    const unsigned prank = (unsigned)(c ^ 1);

    // async-copy one 128-row x 128-col half-slab into smem (4096 16B segs)
    auto issue_half = [&](const float* gsrc, float* stile) {
        #pragma unroll
        for (int k = 0; k < 4; k++) {
            int o = (k << 10) + t;
            int row = o >> 5, seg = (o & 31) << 2;
            const float* src = gsrc + row * 256 + seg;
            unsigned int dst = (unsigned int)__cvta_generic_to_shared(&stile[row * 128 + seg]);
            asm volatile("cp.async.cg.shared.global [%0], [%1], 16;" :: "r"(dst), "l"(src));
        }
        asm volatile("cp.async.commit_group;" ::: "memory");
    };

    // prefetch conv 0 (matrix M0 = index 1)
    {
        const float* g0 = g_mats + 1 * NE_ + c * 128;
        issue_half(g0, Mtile);
        issue_half(g0 + 128 * 256, Mtile + 16384);
    }

    // load this graph's X
    {
        const float* xb = x + b * (N_ * FIN);
        for (int idx = t; idx < N_ * FIN; idx += 1024) {
            float v = xb[idx];
            int i = idx / 5, f = idx - i * 5;
            Xp[idx] = v;
            Xd[i * 6 + f] = dup2(v);
        }
    }

    // peer smem windows for the X exchange
    unsigned int peerXp, peerXd;
    {
        unsigned int lxp = (unsigned int)__cvta_generic_to_shared(Xp);
        unsigned int lxd = (unsigned int)__cvta_generic_to_shared(Xd);
        asm("mapa.shared::cluster.u32 %0, %1, %2;" : "=r"(peerXp) : "r"(lxp), "r"(prank));
        asm("mapa.shared::cluster.u32 %0, %1, %2;" : "=r"(peerXd) : "r"(lxd), "r"(prank));
    }

    unsigned long long acc[FIN];
    const int r0 = ks * 8;

    #pragma unroll 1
    for (int cs = 0; cs < 5; cs++) {
        // matrix order: M0, A, M1, A, M2  ->  index 1,0,2,0,3
        #pragma unroll
        for (int f = 0; f < FIN; f++) acc[f] = 0ull;

        // half 0 ready?
        asm volatile("cp.async.wait_group 1;" ::: "memory");
        __syncthreads();

        #pragma unroll
        for (int r_ = 0; r_ < 8; r_++) {
            int row = r0 + r_;
            unsigned long long kq = *(const unsigned long long*)&Mtile[row * 128 + j2 * 2];
            const unsigned long long* xr = &Xd[row * 6];
            ulonglong2 x01 = *(const ulonglong2*)xr;
            ulonglong2 x23 = *(const ulonglong2*)(xr + 2);
            unsigned long long x4 = xr[4];
            acc[0] = ffma2(kq, x01.x, acc[0]);
            acc[1] = ffma2(kq, x01.y, acc[1]);
            acc[2] = ffma2(kq, x23.x, acc[2]);
            acc[3] = ffma2(kq, x23.y, acc[3]);
            acc[4] = ffma2(kq, x4,    acc[4]);
        }

        // half 1 ready?
        asm volatile("cp.async.wait_group 0;" ::: "memory");
        __syncthreads();

        #pragma unroll
        for (int r_ = 0; r_ < 8; r_++) {
            int row = r0 + r_;
            unsigned long long kq = *(const unsigned long long*)&Mtile[16384 + row * 128 + j2 * 2];
            const unsigned long long* xr = &Xd[(128 + row) * 6];
            ulonglong2 x01 = *(const ulonglong2*)xr;
            ulonglong2 x23 = *(const ulonglong2*)(xr + 2);
            unsigned long long x4 = xr[4];
            acc[0] = ffma2(kq, x01.x, acc[0]);
            acc[1] = ffma2(kq, x01.y, acc[1]);
            acc[2] = ffma2(kq, x23.x, acc[2]);
            acc[3] = ffma2(kq, x23.y, acc[3]);
            acc[4] = ffma2(kq, x4,    acc[4]);
        }

        // stash K-split partials: Ps[j2*5+f][ks]
        #pragma unroll
        for (int f = 0; f < FIN; f++)
            Ps[(j2 * 5 + f) * 18 + ks] = acc[f];
        __syncthreads();   // everyone done reading Mtile & writing Ps

        // prefetch next conv's matrix (order 1,0,2,0,3)
        if (cs < 4) {
            int mi = ((cs + 1) & 1) ? 0 : (((cs + 1) >> 1) + 1);
            const float* gsrc = g_mats + mi * NE_ + c * 128;
            issue_half(gsrc, Mtile);
            issue_half(gsrc + 128 * 256, Mtile + 16384);
        }

        // combine 16 K-splits + 0.1*x + 0.45*agg (+relu on conv #3); update X
        if (t < 320) {
            const ulonglong2* pr = (const ulonglong2*)&Ps[t * 18];
            unsigned long long s = 0ull;
            #pragma unroll
            for (int u = 0; u < 8; u++) {
                ulonglong2 v = pr[u];
                s = fadd2(s, fadd2(v.x, v.y));
            }
            float2 sv = unpack2(s);
            int j2c = t / 5, f = t - j2c * 5;
            int g0c = c * 128 + 2 * j2c;
            float y0 = 0.1f * Xp[g0c * 5 + f]       + 0.45f * sv.x;
            float y1 = 0.1f * Xp[(g0c + 1) * 5 + f] + 0.45f * sv.y;
            if (cs == 2) { y0 = fmaxf(y0, 0.f); y1 = fmaxf(y1, 0.f); }
            Xp[g0c * 5 + f] = y0;  Xp[(g0c + 1) * 5 + f] = y1;
            unsigned long long d0 = dup2(y0), d1 = dup2(y1);
            Xd[g0c * 6 + f] = d0;  Xd[(g0c + 1) * 6 + f] = d1;
            if (cs < 4) {   // peer update (head only needs local half after last conv)
                asm volatile("st.shared::cluster.f32 [%0], %1;" :: "r"(peerXp + (g0c * 5 + f) * 4), "f"(y0));
                asm volatile("st.shared::cluster.f32 [%0], %1;" :: "r"(peerXp + ((g0c + 1) * 5 + f) * 4), "f"(y1));
                asm volatile("st.shared::cluster.b64 [%0], %1;" :: "r"(peerXd + (g0c * 6 + f) * 8), "l"(d0));
                asm volatile("st.shared::cluster.b64 [%0], %1;" :: "r"(peerXd + ((g0c + 1) * 6 + f) * 8), "l"(d1));
            }
        }
        if (cs < 4) {
            asm volatile("barrier.cluster.arrive.aligned;" ::: "memory");
            asm volatile("barrier.cluster.wait.aligned;" ::: "memory");
        } else {
            __syncthreads();
        }
    }

    // ---- head: relu(o @ lin_w + lin_b), pool over this block's 128 nodes ----
    {
        int k = t & 127, h8 = t >> 7;    // 8 node-groups of 16
        float lw0 = lin_w[k], lw1 = lin_w[128 + k], lw2 = lin_w[256 + k],
              lw3 = lin_w[384 + k], lw4 = lin_w[512 + k];
        float lb = lin_b[k];
        float s = 0.f;
        int n0 = c * 128 + h8 * 16;
        #pragma unroll 4
        for (int n = n0; n < n0 + 16; n++) {
            const float* xr = &Xp[n * 5];
            float v = lb;
            v = fmaf(xr[0], lw0, v);
            v = fmaf(xr[1], lw1, v);
            v = fmaf(xr[2], lw2, v);
            v = fmaf(xr[3], lw3, v);
            v = fmaf(xr[4], lw4, v);
            s += fmaxf(v, 0.f);
        }
        Pool[h8 * 128 + k] = s;
    }
    __syncthreads();
    if (t < 128) {
        float p = Pool[t];
        #pragma unroll
        for (int h = 1; h < 8; h++) p += Pool[h * 128 + t];
        if (c) {
            unsigned int lpp = (unsigned int)__cvta_generic_to_shared(&PoolP[t]);
            unsigned int rpp;
            asm("mapa.shared::cluster.u32 %0, %1, %2;" : "=r"(rpp) : "r"(lpp), "r"(prank));
            asm volatile("st.shared::cluster.f32 [%0], %1;" :: "r"(rpp), "f"(p));
        } else {
            Pool[t] = p;
        }
    }
    asm volatile("barrier.cluster.arrive.aligned;" ::: "memory");
    asm volatile("barrier.cluster.wait.aligned;" ::: "memory");
    if (c == 0 && t < 3) {
        float s = fc_b[t];
        for (int k2 = 0; k2 < 128; k2++)
            s = fmaf(Pool[k2] + PoolP[k2], fc_w[k2 * 3 + t], s);
        out[b * 3 + t] = s;
    }
}

// ---------------- launch ----------------
extern "C" void kernel_launch(void* const* d_in, const int* in_sizes, int n_in,
                              void* d_out, int out_size) {
    const float* x     = (const float*)d_in[0];
    const float* ewp   = (const float*)d_in[1];
    const float* a_uc  = (const float*)d_in[2];
    const float* b_uc  = (const float*)d_in[3];
    const float* u_pi  = (const float*)d_in[4];
    const float* u_rb  = (const float*)d_in[5];
    const float* lin_w = (const float*)d_in[6];
    const float* lin_b = (const float*)d_in[7];
    const float* fc_w  = (const float*)d_in[8];
    const float* fc_b  = (const float*)d_in[9];
    // d_in[10] = edge_index, d_in[11] = batch: structure is analytic, unused.
    float* out = (float*)d_out;

    cudaFuncSetAttribute(conv_head_kernel,
                         cudaFuncAttributeMaxDynamicSharedMemorySize, SM_TOTAL);

    deg_scalar_kernel<<<33, 256>>>(ewp, a_uc, b_uc, u_pi, out);
    mats_kernel<<<N_, 256>>>(ewp, u_rb);
    conv_head_kernel<<<2 * B_, 1024, SM_TOTAL>>>(x, lin_w, lin_b, fc_w, fc_b, out);
}